// round 1
// baseline (speedup 1.0000x reference)
#include <cuda_runtime.h>
#include <math.h>

#define D 256
#define KCODES 1024
#define BM 64
#define BN 128
#define BK 16
#define N_MAX 32768

// Scratch (no cudaMalloc allowed)
__device__ float g_w2[KCODES];
__device__ int   g_idx[N_MAX];
__device__ int   g_counts[KCODES];
__device__ float g_partials[N_MAX];

// ---------------------------------------------------------------------------
__global__ void zero_counts_kernel() {
    g_counts[threadIdx.x] = 0;
}

// One warp per code: sum of squares of each codebook row.
__global__ void w2_kernel(const float* __restrict__ w) {
    int warp = (blockIdx.x * blockDim.x + threadIdx.x) >> 5;
    int lane = threadIdx.x & 31;
    if (warp >= KCODES) return;
    const float* row = w + (size_t)warp * D;
    float s = 0.f;
#pragma unroll
    for (int r = 0; r < D / 32; r++) {
        float v = row[lane + 32 * r];
        s += v * v;
    }
#pragma unroll
    for (int o = 16; o; o >>= 1) s += __shfl_xor_sync(0xffffffffu, s, o);
    if (lane == 0) g_w2[warp] = s;
}

// ---------------------------------------------------------------------------
// Fused GEMM (scores = ||w||^2 - 2 z.w) + per-row argmin over all 1024 codes.
// Block: 64 tokens x all codes (8 tiles of 128). 256 threads.
// Thread microtile: 2 rows x 16 cols. Lanes index rows (LDS.64),
// warps index col groups (broadcast reads). Padded smem: conflict-free STS.
__global__ void __launch_bounds__(256, 2)
argmin_kernel(const float* __restrict__ z,
              const float* __restrict__ w,
              float* __restrict__ out_idx_f) {
    __shared__ float As[BK][BM + 2];   // stride 66: conflict-free transpose store
    __shared__ float Bs[BK][BN + 2];   // stride 130
    __shared__ float redV[8][BM];
    __shared__ int   redI[8][BM];
    __shared__ float bestV[BM];
    __shared__ int   bestI[BM];

    const int tid = threadIdx.x;
    const int ty = tid >> 5;   // warp -> 16-col group
    const int tx = tid & 31;   // lane -> row pair
    const int row0 = blockIdx.x * BM;

    if (tid < BM) { bestV[tid] = 3.4e38f; bestI[tid] = 0; }
    __syncthreads();

    for (int ct = 0; ct < KCODES / BN; ct++) {
        float acc[2][16];
#pragma unroll
        for (int i = 0; i < 2; i++)
#pragma unroll
            for (int j = 0; j < 16; j++) acc[i][j] = 0.f;

        for (int kt = 0; kt < D / BK; kt++) {
            // Load A tile (64x16): thread -> m = tid/4, kk = (tid%4)*4
            {
                int m = tid >> 2;
                int kk = (tid & 3) << 2;
                float4 v = *(const float4*)&z[(size_t)(row0 + m) * D + kt * BK + kk];
                As[kk + 0][m] = v.x; As[kk + 1][m] = v.y;
                As[kk + 2][m] = v.z; As[kk + 3][m] = v.w;
            }
            // Load B tile (128x16): two float4 per thread
#pragma unroll
            for (int e2 = 0; e2 < 2; e2++) {
                int e = tid + e2 * 256;
                int n = e >> 2;
                int kk = (e & 3) << 2;
                float4 v = *(const float4*)&w[(size_t)(ct * BN + n) * D + kt * BK + kk];
                Bs[kk + 0][n] = v.x; Bs[kk + 1][n] = v.y;
                Bs[kk + 2][n] = v.z; Bs[kk + 3][n] = v.w;
            }
            __syncthreads();
#pragma unroll
            for (int k = 0; k < BK; k++) {
                float a0 = As[k][2 * tx];
                float a1 = As[k][2 * tx + 1];
#pragma unroll
                for (int j = 0; j < 16; j++) {
                    float b = Bs[k][ty * 16 + j];
                    acc[0][j] += a0 * b;
                    acc[1][j] += a1 * b;
                }
            }
            __syncthreads();
        }

        // Epilogue: scores + local argmin over this thread's 16 columns
#pragma unroll
        for (int i = 0; i < 2; i++) {
            float bv = 3.4e38f;
            int bi = 0;
#pragma unroll
            for (int j = 0; j < 16; j++) {
                int c = ct * BN + ty * 16 + j;
                float s = g_w2[c] - 2.f * acc[i][j];
                if (s < bv) { bv = s; bi = c; }   // j ascending => first-min tie-break
            }
            redV[ty][2 * tx + i] = bv;
            redI[ty][2 * tx + i] = bi;
        }
        __syncthreads();
        if (tid < BM) {
            float bv = bestV[tid];
            int bi = bestI[tid];
#pragma unroll
            for (int wq = 0; wq < 8; wq++) {   // ascending col groups
                float v = redV[wq][tid];
                int id = redI[wq][tid];
                if (v < bv || (v == bv && id < bi)) { bv = v; bi = id; }
            }
            bestV[tid] = bv; bestI[tid] = bi;
        }
        __syncthreads();
    }

    if (tid < BM) {
        int row = row0 + tid;
        int bi = bestI[tid];
        g_idx[row] = bi;
        out_idx_f[row] = (float)bi;
        atomicAdd(&g_counts[bi], 1);
    }
}

// ---------------------------------------------------------------------------
// Gather z_q = weight[idx], write straight-through output, per-token sq-diff sum.
__global__ void gather_kernel(const float* __restrict__ z,
                              const float* __restrict__ w,
                              float* __restrict__ out_zq) {
    int token = blockIdx.x;
    int t = threadIdx.x;  // 0..255 == dim
    int idx = g_idx[token];
    float zq = w[(size_t)idx * D + t];
    float zv = z[(size_t)token * D + t];
    out_zq[(size_t)token * D + t] = zq;   // z + sg(z_q - z) == z_q
    float d = zq - zv;

    __shared__ float red[256];
    red[t] = d * d;
    __syncthreads();
#pragma unroll
    for (int o = 128; o; o >>= 1) {
        if (t < o) red[t] += red[t + o];
        __syncthreads();
    }
    if (t == 0) g_partials[token] = red[0];
}

// ---------------------------------------------------------------------------
__global__ void finalize_kernel(float* __restrict__ out_loss,
                                float* __restrict__ out_perp, int N) {
    __shared__ float red[1024];
    int t = threadIdx.x;

    // Loss: deterministic two-stage reduction of per-token partials
    float s = 0.f;
    for (int i = t; i < N; i += 1024) s += g_partials[i];
    red[t] = s;
    __syncthreads();
#pragma unroll
    for (int o = 512; o; o >>= 1) {
        if (t < o) red[t] += red[t + o];
        __syncthreads();
    }
    if (t == 0) out_loss[0] = 0.25f * red[0] / (float)(N * D);
    __syncthreads();

    // Perplexity from counts
    float e = (float)g_counts[t] / (float)N;
    red[t] = e * logf(e + 1e-10f);
    __syncthreads();
#pragma unroll
    for (int o = 512; o; o >>= 1) {
        if (t < o) red[t] += red[t + o];
        __syncthreads();
    }
    if (t == 0) out_perp[0] = expf(-red[0]);
}

// ---------------------------------------------------------------------------
extern "C" void kernel_launch(void* const* d_in, const int* in_sizes, int n_in,
                              void* d_out, int out_size) {
    const float* z = (const float*)d_in[0];
    const float* w = (const float*)d_in[1];
    float* out = (float*)d_out;

    const int N = in_sizes[0] / D;  // 32768

    // Output layout (reference tuple order, all fp32):
    // [ loss | z_q_st (N*D) | indices (N) | perplexity ]
    float* out_loss = out;
    float* out_zq   = out + 1;
    float* out_idx  = out + 1 + (size_t)N * D;
    float* out_perp = out + 1 + (size_t)N * D + N;

    zero_counts_kernel<<<1, KCODES>>>();
    w2_kernel<<<KCODES / 8, 256>>>(w);
    argmin_kernel<<<N / BM, 256>>>(z, w, out_idx);
    gather_kernel<<<N, 256>>>(z, w, out_zq);
    finalize_kernel<<<1, 1024>>>(out_loss, out_perp, N);
}

// round 4
// speedup vs baseline: 3.8674x; 3.8674x over previous
#include <cuda_runtime.h>
#include <cuda_fp16.h>
#include <math.h>
#include <stdint.h>
#include <float.h>

#define D 256
#define KCODES 1024
#define N_MAX 32768
#define TAU 0.15f

#define BM 128
#define BN 128
#define NC_IT (KCODES / BN)   // 8

// Scratch (no cudaMalloc allowed)
__device__ float g_w2[KCODES];
__device__ int   g_idx[N_MAX];
__device__ int   g_counts[KCODES];
__device__ float g_partials[N_MAX];
__device__ int   g_flag[N_MAX];
__device__ int   g_nflag;
__device__ __align__(128) __half g_zh[(size_t)N_MAX * D];   // 16MB
__device__ __align__(128) __half g_wh[(size_t)KCODES * D];  // 512KB

// ============================ PTX helpers (all non-'a' arch) =================
__device__ __forceinline__ uint32_t smem_u32(const void* p) {
    uint32_t a;
    asm("{ .reg .u64 t; cvta.to.shared.u64 t, %1; cvt.u32.u64 %0, t; }"
        : "=r"(a) : "l"(p));
    return a;
}
__device__ __forceinline__ void cp16(uint32_t dst, const void* src) {
    asm volatile("cp.async.cg.shared.global [%0], [%1], 16;" :: "r"(dst), "l"(src));
}
#define CP_COMMIT() asm volatile("cp.async.commit_group;" ::: "memory")
#define CP_WAIT0()  asm volatile("cp.async.wait_group 0;"  ::: "memory")

__device__ __forceinline__ void ldsm4(uint32_t* r, uint32_t addr) {
    asm volatile("ldmatrix.sync.aligned.m8n8.x4.shared.b16 {%0,%1,%2,%3}, [%4];"
        : "=r"(r[0]), "=r"(r[1]), "=r"(r[2]), "=r"(r[3]) : "r"(addr));
}
__device__ __forceinline__ void mma16816(float* c, const uint32_t* a,
                                         uint32_t b0, uint32_t b1) {
    asm volatile(
        "mma.sync.aligned.m16n8k16.row.col.f32.f16.f16.f32 "
        "{%0,%1,%2,%3}, {%4,%5,%6,%7}, {%8,%9}, {%0,%1,%2,%3};"
        : "+f"(c[0]), "+f"(c[1]), "+f"(c[2]), "+f"(c[3])
        : "r"(a[0]), "r"(a[1]), "r"(a[2]), "r"(a[3]), "r"(b0), "r"(b1));
}

// SMEM layout (dynamic)
#define OFF_A   0
#define OFF_B0  65536
#define OFF_B1  131072
#define OFF_RB1 196608      // float[256]
#define OFF_RI1 197632      // int[256]
#define OFF_RB2 198656      // float[256]
#define OFF_W2  199680      // float[1024]
#define SMEM_BYTES 203776

// ============================ Small kernels ==================================
__global__ void zero_kernel() {
    g_counts[threadIdx.x] = 0;
    if (threadIdx.x == 0) g_nflag = 0;
}

__global__ void convert_kernel(const float* __restrict__ z, const float* __restrict__ w) {
    const int nz4 = N_MAX * D / 4;
    const int nw4 = KCODES * D / 4;
    const int tot = nz4 + nw4;
    for (int i = blockIdx.x * blockDim.x + threadIdx.x; i < tot;
         i += gridDim.x * blockDim.x) {
        float4 v = (i < nz4) ? ((const float4*)z)[i] : ((const float4*)w)[i - nz4];
        __half2 h0 = __floats2half2_rn(v.x, v.y);
        __half2 h1 = __floats2half2_rn(v.z, v.w);
        uint2 u;
        u.x = *(uint32_t*)&h0;
        u.y = *(uint32_t*)&h1;
        if (i < nz4) ((uint2*)g_zh)[i] = u;
        else         ((uint2*)g_wh)[i - nz4] = u;
    }
}

__global__ void w2_kernel(const float* __restrict__ w) {
    int warp = (blockIdx.x * blockDim.x + threadIdx.x) >> 5;
    int lane = threadIdx.x & 31;
    if (warp >= KCODES) return;
    const float* row = w + (size_t)warp * D;
    float s = 0.f;
#pragma unroll
    for (int r = 0; r < D / 32; r++) { float v = row[lane + 32 * r]; s += v * v; }
#pragma unroll
    for (int o = 16; o; o >>= 1) s += __shfl_xor_sync(0xffffffffu, s, o);
    if (lane == 0) g_w2[warp] = s;
}

// ============================ GEMM + fused argmin ============================
// scores = ||w||^2 - 2 z.w in fp16 mma.sync; best + second-best per token;
// near-ties flagged for exact fp32 rescore.
__global__ void __launch_bounds__(256, 1)
vq_gemm_kernel(float* __restrict__ out_idx_f) {
    extern __shared__ __align__(128) char smem[];
    const int tid = threadIdx.x;
    const int lane = tid & 31;
    const int wid = tid >> 5;
    const int wm = wid & 3;          // 4 row bands of 32
    const int wn = wid >> 2;         // 2 col bands of 64
    const int row_w = wm * 32;
    const int col_w = wn * 64;
    const int row0 = blockIdx.x * BM;

    const uint32_t sb = smem_u32(smem);
    const uint32_t sA = sb + OFF_A;
    float* redB1 = (float*)(smem + OFF_RB1);
    int*   redI1 = (int*)(smem + OFF_RI1);
    float* redB2 = (float*)(smem + OFF_RB2);
    float* sw2   = (float*)(smem + OFF_W2);

    // preload ||w||^2
    for (int i = tid; i < KCODES; i += 256) sw2[i] = g_w2[i];

    // ---- cp.async A tile (128 x 256 fp16, xor-swizzled 16B chunks) ----
    {
        const __half* zA = g_zh + (size_t)row0 * D;
#pragma unroll
        for (int i = 0; i < 16; i++) {
            int idx = tid + i * 256;
            int r = idx >> 5, c = idx & 31;
            cp16(sA + r * 512 + ((c ^ (r & 7)) << 4), zA + (size_t)r * D + c * 8);
        }
        CP_COMMIT();
    }
    // ---- cp.async B tile nc=0 ----
    {
        const __half* src = g_wh;
#pragma unroll
        for (int i = 0; i < 16; i++) {
            int idx = tid + i * 256;
            int r = idx >> 5, c = idx & 31;
            cp16(sb + OFF_B0 + r * 512 + ((c ^ (r & 7)) << 4), src + (size_t)r * D + c * 8);
        }
        CP_COMMIT();
    }

    float rb1 = FLT_MAX, rb2 = FLT_MAX;
    int ri1 = 0;
    const int within = lane & 7;
    const int sel = lane >> 3;

    for (int nc = 0; nc < NC_IT; nc++) {
        CP_WAIT0();
        __syncthreads();
        if (nc < NC_IT - 1) {
            const __half* src = g_wh + (size_t)(nc + 1) * BN * D;
            uint32_t dstb = sb + ((nc + 1) & 1 ? OFF_B1 : OFF_B0);
#pragma unroll
            for (int i = 0; i < 16; i++) {
                int idx = tid + i * 256;
                int r = idx >> 5, c = idx & 31;
                cp16(dstb + r * 512 + ((c ^ (r & 7)) << 4), src + (size_t)r * D + c * 8);
            }
            CP_COMMIT();
        }
        const uint32_t sBc = sb + ((nc & 1) ? OFF_B1 : OFF_B0);

        float cacc[2][8][4];
#pragma unroll
        for (int mi = 0; mi < 2; mi++)
#pragma unroll
            for (int ni = 0; ni < 8; ni++)
#pragma unroll
                for (int e = 0; e < 4; e++) cacc[mi][ni][e] = 0.f;

#pragma unroll
        for (int ks = 0; ks < 16; ks++) {
            uint32_t a[2][4];
#pragma unroll
            for (int mi = 0; mi < 2; mi++) {
                int ra = row_w + mi * 16 + ((sel & 1) << 3) + within;
                int ca = ks * 2 + (sel >> 1);
                ldsm4(a[mi], sA + ra * 512 + ((ca ^ (ra & 7)) << 4));
            }
            uint32_t b[4][4];
#pragma unroll
            for (int p = 0; p < 4; p++) {
                int rb = col_w + p * 16 + ((sel >> 1) << 3) + within;
                int cb = ks * 2 + (sel & 1);
                ldsm4(b[p], sBc + rb * 512 + ((cb ^ (rb & 7)) << 4));
            }
#pragma unroll
            for (int mi = 0; mi < 2; mi++)
#pragma unroll
                for (int ni = 0; ni < 8; ni++) {
                    const int p = ni >> 1;
                    if (ni & 1) mma16816(cacc[mi][ni], a[mi], b[p][2], b[p][3]);
                    else        mma16816(cacc[mi][ni], a[mi], b[p][0], b[p][1]);
                }
        }

        // ---- epilogue: per-row (best, idx, second) over this 128-col chunk ----
#pragma unroll
        for (int mi = 0; mi < 2; mi++)
#pragma unroll
            for (int h = 0; h < 2; h++) {
                float v1 = FLT_MAX, v2 = FLT_MAX;
                int j1 = 0;
#pragma unroll
                for (int ni = 0; ni < 8; ni++)
#pragma unroll
                    for (int e = 0; e < 2; e++) {
                        int gcol = nc * BN + col_w + ni * 8 + ((lane & 3) << 1) + e;
                        float s = sw2[gcol] - 2.f * cacc[mi][ni][h * 2 + e];
                        if (s < v1) { v2 = v1; v1 = s; j1 = gcol; }
                        else if (s < v2) v2 = s;
                    }
                // butterfly across the 4 lanes sharing this row
#pragma unroll
                for (int off = 1; off <= 2; off <<= 1) {
                    float o1 = __shfl_xor_sync(0xffffffffu, v1, off);
                    int oj   = __shfl_xor_sync(0xffffffffu, j1, off);
                    float o2 = __shfl_xor_sync(0xffffffffu, v2, off);
                    if (o1 < v1 || (o1 == v1 && oj < j1)) {
                        v2 = fminf(v1, o2); v1 = o1; j1 = oj;
                    } else {
                        v2 = fminf(v2, o1);
                    }
                }
                if ((lane & 3) == 0) {
                    int r = row_w + mi * 16 + (lane >> 2) + h * 8;
                    redB1[wn * 128 + r] = v1;
                    redI1[wn * 128 + r] = j1;
                    redB2[wn * 128 + r] = v2;
                }
            }
        __syncthreads();
        if (tid < 128) {
            float a1 = redB1[tid], a2 = redB2[tid];
            int aj = redI1[tid];
            float c1 = redB1[128 + tid], c2 = redB2[128 + tid];
            int cj = redI1[128 + tid];
            if (c1 < a1 || (c1 == a1 && cj < aj)) { a2 = fminf(a1, c2); a1 = c1; aj = cj; }
            else a2 = fminf(a2, c1);
            if (a1 < rb1 || (a1 == rb1 && aj < ri1)) { rb2 = fminf(rb1, a2); rb1 = a1; ri1 = aj; }
            else rb2 = fminf(rb2, a1);
        }
        __syncthreads();
    }

    if (tid < 128) {
        int row = row0 + tid;
        g_idx[row] = ri1;
        out_idx_f[row] = (float)ri1;
        atomicAdd(&g_counts[ri1], 1);
        if (rb2 - rb1 < TAU) {
            int p = atomicAdd(&g_nflag, 1);
            g_flag[p] = row;
        }
    }
}

// ============================ Exact rescore (4 tokens / block) ===============
__global__ void rescore_kernel(const float* __restrict__ z, const float* __restrict__ w,
                               float* __restrict__ out_idx_f) {
    __shared__ __align__(16) float zs[4][D];
    __shared__ float rv[4][256];
    __shared__ int   rix[4][256];
    const int tid = threadIdx.x;
    const int nf = g_nflag;
    for (int base = blockIdx.x * 4; base < nf; base += gridDim.x * 4) {
        __syncthreads();
        for (int j = tid; j < 4 * D; j += 256) {
            int t = j >> 8;
            int tok = (base + t < nf) ? g_flag[base + t] : g_flag[base];
            zs[t][j & 255] = z[(size_t)tok * D + (j & 255)];
        }
        __syncthreads();
        float best[4] = {FLT_MAX, FLT_MAX, FLT_MAX, FLT_MAX};
        int bidx[4] = {0, 0, 0, 0};
#pragma unroll
        for (int cc = 0; cc < 4; cc++) {
            int c = cc * 256 + tid;
            const float4* wr = (const float4*)(w + (size_t)c * D);
            float a0 = 0.f, a1 = 0.f, a2 = 0.f, a3 = 0.f;
            for (int k = 0; k < D / 4; k++) {
                float4 wv = wr[k];
                float4 z0 = ((const float4*)zs[0])[k];
                float4 z1 = ((const float4*)zs[1])[k];
                float4 z2 = ((const float4*)zs[2])[k];
                float4 z3 = ((const float4*)zs[3])[k];
                a0 += wv.x * z0.x + wv.y * z0.y + wv.z * z0.z + wv.w * z0.w;
                a1 += wv.x * z1.x + wv.y * z1.y + wv.z * z1.z + wv.w * z1.w;
                a2 += wv.x * z2.x + wv.y * z2.y + wv.z * z2.z + wv.w * z2.w;
                a3 += wv.x * z3.x + wv.y * z3.y + wv.z * z3.z + wv.w * z3.w;
            }
            float w2c = g_w2[c];
            float s0 = w2c - 2.f * a0, s1 = w2c - 2.f * a1;
            float s2 = w2c - 2.f * a2, s3 = w2c - 2.f * a3;
            if (s0 < best[0]) { best[0] = s0; bidx[0] = c; }
            if (s1 < best[1]) { best[1] = s1; bidx[1] = c; }
            if (s2 < best[2]) { best[2] = s2; bidx[2] = c; }
            if (s3 < best[3]) { best[3] = s3; bidx[3] = c; }
        }
#pragma unroll
        for (int t = 0; t < 4; t++) { rv[t][tid] = best[t]; rix[t][tid] = bidx[t]; }
        __syncthreads();
        for (int off = 128; off; off >>= 1) {
            if (tid < off) {
#pragma unroll
                for (int t = 0; t < 4; t++) {
                    float ov = rv[t][tid + off]; int oi = rix[t][tid + off];
                    if (ov < rv[t][tid] || (ov == rv[t][tid] && oi < rix[t][tid])) {
                        rv[t][tid] = ov; rix[t][tid] = oi;
                    }
                }
            }
            __syncthreads();
        }
        if (tid < 4 && base + tid < nf) {
            int tok = g_flag[base + tid];
            int ni = rix[tid][0], old = g_idx[tok];
            if (ni != old) {
                atomicSub(&g_counts[old], 1);
                atomicAdd(&g_counts[ni], 1);
                g_idx[tok] = ni;
                out_idx_f[tok] = (float)ni;
            }
        }
    }
}

// ============================ Gather + loss ==================================
// float4 loads (w, z are 16B-aligned); SCALAR stores to out_zq (d_out+1 is
// only 4B-aligned -- float4 stores there trap with misaligned address).
__global__ void gather_kernel(const float* __restrict__ z, const float* __restrict__ w,
                              float* __restrict__ out_zq) {
    __shared__ float sred[8];
    const int tid = threadIdx.x;
    const int sub = tid >> 6;
    const int t = tid & 63;
    const int token = blockIdx.x * 4 + sub;
    const int idx = g_idx[token];
    float4 q = *(const float4*)&w[(size_t)idx * D + t * 4];
    float4 v = *(const float4*)&z[(size_t)token * D + t * 4];
    float* o = &out_zq[(size_t)token * D + t * 4];
    o[0] = q.x; o[1] = q.y; o[2] = q.z; o[3] = q.w;
    float dx = q.x - v.x, dy = q.y - v.y, dz = q.z - v.z, dw = q.w - v.w;
    float s = dx * dx + dy * dy + dz * dz + dw * dw;
#pragma unroll
    for (int o2 = 16; o2; o2 >>= 1) s += __shfl_xor_sync(0xffffffffu, s, o2);
    if ((tid & 31) == 0) sred[tid >> 5] = s;
    __syncthreads();
    if (tid < 4) g_partials[blockIdx.x * 4 + tid] = sred[2 * tid] + sred[2 * tid + 1];
}

__global__ void finalize_kernel(float* __restrict__ out_loss,
                                float* __restrict__ out_perp, int N) {
    __shared__ float red[1024];
    int t = threadIdx.x;
    float s = 0.f;
    for (int i = t; i < N; i += 1024) s += g_partials[i];
    red[t] = s;
    __syncthreads();
#pragma unroll
    for (int o = 512; o; o >>= 1) {
        if (t < o) red[t] += red[t + o];
        __syncthreads();
    }
    if (t == 0) out_loss[0] = 0.25f * red[0] / (float)(N * D);
    __syncthreads();
    float e = (float)g_counts[t] / (float)N;
    red[t] = e * logf(e + 1e-10f);
    __syncthreads();
#pragma unroll
    for (int o = 512; o; o >>= 1) {
        if (t < o) red[t] += red[t + o];
        __syncthreads();
    }
    if (t == 0) out_perp[0] = expf(-red[0]);
}

// ============================================================================
extern "C" void kernel_launch(void* const* d_in, const int* in_sizes, int n_in,
                              void* d_out, int out_size) {
    const float* z = (const float*)d_in[0];
    const float* w = (const float*)d_in[1];
    float* out = (float*)d_out;

    const int N = in_sizes[0] / D;  // 32768

    float* out_loss = out;
    float* out_zq   = out + 1;
    float* out_idx  = out + 1 + (size_t)N * D;
    float* out_perp = out + 1 + (size_t)N * D + N;

    cudaFuncSetAttribute(vq_gemm_kernel,
                         cudaFuncAttributeMaxDynamicSharedMemorySize, SMEM_BYTES);

    zero_kernel<<<1, KCODES>>>();
    convert_kernel<<<4096, 256>>>(z, w);
    w2_kernel<<<128, 256>>>(w);
    vq_gemm_kernel<<<N / BM, 256, SMEM_BYTES>>>(out_idx);
    rescore_kernel<<<128, 256>>>(z, w, out_idx);
    gather_kernel<<<N / 4, 256>>>(z, w, out_zq);
    finalize_kernel<<<1, 1024>>>(out_loss, out_perp, N);
}